// round 15
// baseline (speedup 1.0000x reference)
#include <cuda_runtime.h>
#include <cuda_bf16.h>
#include <math.h>
#include <cstdint>

#define BB   2
#define SEQ  2048
#define HIDN 2048
#define NH   16
#define NKV  4
#define HD   128

// ============================================================
// helpers
// ============================================================
__device__ __forceinline__ uint32_t smem_u32(const void* p) {
    uint32_t a;
    asm("{ .reg .u64 t; cvta.to.shared.u64 t, %1; cvt.u32.u64 %0, t; }" : "=r"(a) : "l"(p));
    return a;
}
__device__ __forceinline__ void ldsm_x4(uint32_t& r0, uint32_t& r1, uint32_t& r2, uint32_t& r3,
                                        uint32_t addr) {
    asm volatile("ldmatrix.sync.aligned.m8n8.x4.shared.b16 {%0,%1,%2,%3}, [%4];"
                 : "=r"(r0), "=r"(r1), "=r"(r2), "=r"(r3) : "r"(addr));
}
__device__ __forceinline__ void ldsm_x4_t(uint32_t& r0, uint32_t& r1, uint32_t& r2, uint32_t& r3,
                                          uint32_t addr) {
    asm volatile("ldmatrix.sync.aligned.m8n8.x4.trans.shared.b16 {%0,%1,%2,%3}, [%4];"
                 : "=r"(r0), "=r"(r1), "=r"(r2), "=r"(r3) : "r"(addr));
}
__device__ __forceinline__ void mma_bf16(float* c, const uint32_t* a, const uint32_t* b) {
    asm volatile("mma.sync.aligned.m16n8k16.row.col.f32.bf16.bf16.f32 "
                 "{%0,%1,%2,%3}, {%4,%5,%6,%7}, {%8,%9}, {%0,%1,%2,%3};"
                 : "+f"(c[0]), "+f"(c[1]), "+f"(c[2]), "+f"(c[3])
                 : "r"(a[0]), "r"(a[1]), "r"(a[2]), "r"(a[3]), "r"(b[0]), "r"(b[1]));
}
__device__ __forceinline__ void cp_async16(uint32_t saddr, const void* gptr) {
    asm volatile("cp.async.cg.shared.global [%0], [%1], 16;"
                 :: "r"(saddr), "l"(__cvta_generic_to_global(gptr)));
}
__device__ __forceinline__ float fexp2(float t) {
    t = fmaxf(t, -126.0f);
    float fi = floorf(t);
    float f = t - fi;
    float p =             1.5403530e-4f;
    p = fmaf(p, f, 1.3333558e-3f);
    p = fmaf(p, f, 9.6181291e-3f);
    p = fmaf(p, f, 5.5504109e-2f);
    p = fmaf(p, f, 2.4022651e-1f);
    p = fmaf(p, f, 6.9314718e-1f);
    p = fmaf(p, f, 1.0f);
    return p * __int_as_float(((int)fi + 127) << 23);
}
__device__ __forceinline__ uint32_t pack_bf16x2(float lo, float hi) {
    __nv_bfloat162 t;
    t.x = __float2bfloat16(lo);
    t.y = __float2bfloat16(hi);
    return *(uint32_t*)&t;
}

// -------- scratch (device globals) --------
__device__ __nv_bfloat16 g_xh[(size_t)BB * SEQ * HIDN], g_xl[(size_t)BB * SEQ * HIDN];
#define NQKV 3072
__device__ __nv_bfloat16 g_wh[(size_t)NQKV * HIDN], g_wl[(size_t)NQKV * HIDN];
__device__ __nv_bfloat16 g_woh[(size_t)NH * HD * HIDN], g_wol[(size_t)NH * HD * HIDN];

__device__ __nv_bfloat16 g_qsh[(size_t)BB * NH * SEQ * HD],  g_qsl[(size_t)BB * NH * SEQ * HD];
__device__ __nv_bfloat16 g_ksh[(size_t)BB * NKV * SEQ * HD], g_ksl[(size_t)BB * NKV * SEQ * HD];
__device__ __nv_bfloat16 g_vsh[(size_t)BB * NKV * SEQ * HD], g_vsl[(size_t)BB * NKV * SEQ * HD];
__device__ __nv_bfloat16 g_oh[(size_t)BB * SEQ * NH * HD],  g_ol[(size_t)BB * SEQ * NH * HD];

// ============================================================
// fp32 -> (hi, lo) bf16 split
// ============================================================
__global__ void split_fp32(const float* __restrict__ x,
                           __nv_bfloat16* __restrict__ h, __nv_bfloat16* __restrict__ l, int n)
{
    int i = blockIdx.x * blockDim.x + threadIdx.x;
    if (i < n) {
        float v = x[i];
        __nv_bfloat16 hi = __float2bfloat16(v);
        h[i] = hi;
        l[i] = __float2bfloat16(v - __bfloat162float(hi));
    }
}

// ============================================================
// W[K,N] fp32 -> Wt_hi/Wt_lo [N,K] bf16 (transpose + split)
// ============================================================
__global__ void transpose_split(const float* __restrict__ W,
                                __nv_bfloat16* __restrict__ Th, __nv_bfloat16* __restrict__ Tl,
                                int K, int N)
{
    __shared__ float t[32][33];
    const int n0 = blockIdx.x * 32, k0 = blockIdx.y * 32;
    const int tx = threadIdx.x, ty = threadIdx.y;
    for (int i = ty; i < 32; i += 8)
        t[i][tx] = W[(size_t)(k0 + i) * N + n0 + tx];
    __syncthreads();
    for (int i = ty; i < 32; i += 8) {
        float v = t[tx][i];
        __nv_bfloat16 hi = __float2bfloat16(v);
        float r = v - __bfloat162float(hi);
        Th[(size_t)(n0 + i) * K + k0 + tx] = hi;
        Tl[(size_t)(n0 + i) * K + k0 + tx] = __float2bfloat16(r);
    }
}

#define LDA 40

// ============================================================
// gemm3: 128x128 CTA tile, 4 warps (2x2) 64x64 warp tiles,
// BK=32, 2-stage cp.async, 2 CTAs/SM, B-fragments streamed.
// epi==0 -> fp32 row-major Cf; epi==1 -> fused QKV scatter.
// ============================================================
#define G3_TILE (128 * LDA * 2)
#define G3_STAGE (4 * G3_TILE)
#define G3_SMEM (2 * G3_STAGE)

__global__ void __launch_bounds__(128, 2) gemm3(
    const __nv_bfloat16* __restrict__ Ah_, const __nv_bfloat16* __restrict__ Al_,
    const __nv_bfloat16* __restrict__ Bh_, const __nv_bfloat16* __restrict__ Bl_,
    float* __restrict__ Cf,
    __nv_bfloat16* __restrict__ Qh, __nv_bfloat16* __restrict__ Ql,
    __nv_bfloat16* __restrict__ Kh, __nv_bfloat16* __restrict__ Kl,
    __nv_bfloat16* __restrict__ Vh, __nv_bfloat16* __restrict__ Vl,
    int Nd, int Kd, int epi)
{
    extern __shared__ char sm[];
    const uint32_t sb = smem_u32(sm);
    const int tid = threadIdx.x, lane = tid & 31, wid = tid >> 5;
    const int m0 = blockIdx.y * 128, n0 = blockIdx.x * 128;
    const int m_off = (wid >> 1) * 64;
    const int n_off = (wid & 1) * 64;

    const int r0 = tid >> 2;
    const int c8 = (tid & 3) * 8;

    const __nv_bfloat16* gp[4] = {
        Ah_ + (size_t)m0 * Kd, Al_ + (size_t)m0 * Kd,
        Bh_ + (size_t)n0 * Kd, Bl_ + (size_t)n0 * Kd };

    const int nchunk = Kd >> 5;

    auto load_chunk = [&](int c) {
        const int k0 = c << 5;
        const uint32_t stg = sb + (uint32_t)(c & 1) * G3_STAGE;
#pragma unroll
        for (int t = 0; t < 4; t++) {
#pragma unroll
            for (int p = 0; p < 4; p++) {
                const int r = r0 + p * 32;
                cp_async16(stg + (uint32_t)t * G3_TILE + (uint32_t)(r * LDA + c8) * 2,
                           gp[t] + (size_t)r * Kd + k0 + c8);
            }
        }
        asm volatile("cp.async.commit_group;" ::: "memory");
    };

    const int a_row = ((lane >> 3) & 1) * 8 + (lane & 7);
    const int a_kh  = (lane >> 4) * 8;
    const int b_row = ((lane >> 4) & 1) * 8 + (lane & 7);
    const int b_kh  = ((lane >> 3) & 1) * 8;

    float acc[4][8][4];
#pragma unroll
    for (int i = 0; i < 4; i++)
#pragma unroll
        for (int j = 0; j < 8; j++)
#pragma unroll
            for (int q = 0; q < 4; q++) acc[i][j][q] = 0.f;

    load_chunk(0);
    for (int c = 0; c < nchunk; c++) {
        if (c + 1 < nchunk) {
            load_chunk(c + 1);
            asm volatile("cp.async.wait_group 1;" ::: "memory");
        } else {
            asm volatile("cp.async.wait_group 0;" ::: "memory");
        }
        __syncthreads();

        const uint32_t stg = sb + (uint32_t)(c & 1) * G3_STAGE;
        const uint32_t sAh = stg;
        const uint32_t sAl = stg + G3_TILE;
        const uint32_t sBh = stg + 2 * G3_TILE;
        const uint32_t sBl = stg + 3 * G3_TILE;

#pragma unroll
        for (int ks = 0; ks < 2; ks++) {
            uint32_t ah[4][4], al[4][4];
#pragma unroll
            for (int mi = 0; mi < 4; mi++) {
                const uint32_t off =
                    (uint32_t)((m_off + mi * 16 + a_row) * LDA + ks * 16 + a_kh) * 2;
                ldsm_x4(ah[mi][0], ah[mi][1], ah[mi][2], ah[mi][3], sAh + off);
                ldsm_x4(al[mi][0], al[mi][1], al[mi][2], al[mi][3], sAl + off);
            }
#pragma unroll
            for (int nb = 0; nb < 4; nb++) {
                uint32_t bh[2][2], bl[2][2];
                const uint32_t off =
                    (uint32_t)((n_off + nb * 16 + b_row) * LDA + ks * 16 + b_kh) * 2;
                ldsm_x4(bh[0][0], bh[0][1], bh[1][0], bh[1][1], sBh + off);
                ldsm_x4(bl[0][0], bl[0][1], bl[1][0], bl[1][1], sBl + off);
#pragma unroll
                for (int mi = 0; mi < 4; mi++) {
#pragma unroll
                    for (int t2 = 0; t2 < 2; t2++) {
                        float* a = acc[mi][2 * nb + t2];
                        mma_bf16(a, ah[mi], bh[t2]);
                        mma_bf16(a, ah[mi], bl[t2]);
                        mma_bf16(a, al[mi], bh[t2]);
                    }
                }
            }
        }
        __syncthreads();
    }

    const int erow = lane >> 2, ecol = (lane & 3) * 2;
    if (epi == 0) {
#pragma unroll
        for (int mi = 0; mi < 4; mi++)
#pragma unroll
            for (int ni = 0; ni < 8; ni++) {
                const int row = m0 + m_off + mi * 16 + erow;
                const int col = n0 + n_off + ni * 8 + ecol;
                float2 v0 = make_float2(acc[mi][ni][0], acc[mi][ni][1]);
                float2 v1 = make_float2(acc[mi][ni][2], acc[mi][ni][3]);
                *(float2*)(Cf + (size_t)row * Nd + col)       = v0;
                *(float2*)(Cf + (size_t)(row + 8) * Nd + col) = v1;
            }
    } else {
        __nv_bfloat16 *Dh, *Dl;
        int hh, heads;
        {
            const int colbase = n0 + n_off;
            if (colbase < 2048)      { Dh = Qh; Dl = Ql; hh = colbase >> 7;          heads = NH; }
            else if (colbase < 2560) { Dh = Kh; Dl = Kl; hh = (colbase - 2048) >> 7; heads = NKV; }
            else                     { Dh = Vh; Dl = Vl; hh = (colbase - 2560) >> 7; heads = NKV; }
        }
#pragma unroll
        for (int mi = 0; mi < 4; mi++)
#pragma unroll
            for (int ni = 0; ni < 8; ni++) {
                const int d = ((n_off & 64) + ni * 8 + ecol) & 127;
#pragma unroll
                for (int rr = 0; rr < 2; rr++) {
                    const int row = m0 + m_off + mi * 16 + erow + rr * 8;
                    const int bb = row >> 11, s = row & (SEQ - 1);
                    const size_t g = ((size_t)(bb * heads + hh) * SEQ + s) * HD + d;
                    float v0 = acc[mi][ni][rr * 2 + 0];
                    float v1 = acc[mi][ni][rr * 2 + 1];
                    __nv_bfloat16 h0 = __float2bfloat16(v0);
                    __nv_bfloat16 h1 = __float2bfloat16(v1);
                    __nv_bfloat162 hp; hp.x = h0; hp.y = h1;
                    *(__nv_bfloat162*)(Dh + g) = hp;
                    __nv_bfloat162 lp;
                    lp.x = __float2bfloat16(v0 - __bfloat162float(h0));
                    lp.y = __float2bfloat16(v1 - __bfloat162float(h1));
                    *(__nv_bfloat162*)(Dl + g) = lp;
                }
            }
    }
}

// ============================================================
// RoPE in-place; 128 threads = 2 rows per block
// ============================================================
__global__ void rope_inplace(__nv_bfloat16* __restrict__ h, __nv_bfloat16* __restrict__ l)
{
    const int ty = threadIdx.x >> 6;
    const int idx = blockIdx.x * 2 + ty;
    const int s = idx & (SEQ - 1);
    const size_t base = (size_t)idx * HD;
    const int i = threadIdx.x & 63;

    float x0 = __bfloat162float(h[base + 2 * i])     + __bfloat162float(l[base + 2 * i]);
    float x1 = __bfloat162float(h[base + 2 * i + 1]) + __bfloat162float(l[base + 2 * i + 1]);
    float inv = exp2f(-(float)i * (13.287712379549449f / 64.f));
    float ang = (float)s * inv;
    float sn, cs;
    sincosf(ang, &sn, &cs);
    float o0 = x0 * cs - x1 * sn;
    float o1 = x0 * sn + x1 * cs;
    __syncthreads();
    __nv_bfloat16 h0 = __float2bfloat16(o0);
    __nv_bfloat16 h1 = __float2bfloat16(o1);
    h[base + i]      = h0;
    h[base + i + 64] = h1;
    l[base + i]      = __float2bfloat16(o0 - __bfloat162float(h0));
    l[base + i + 64] = __float2bfloat16(o1 - __bfloat162float(h1));
}

// ============================================================
// FA2-style HMMA flash attention (unchanged from R13)
// ============================================================
#define ALDQ 136
#define NQH 0
#define NQL (128 * ALDQ * 2)
#define NKV0 (2 * 128 * ALDQ * 2)
#define NKVT (64 * ALDQ * 2)
#define NATTN_SMEM (NKV0 + 8 * NKVT)

#define SCL2E 0.12751744f

__global__ void __launch_bounds__(256, 1) attn_hmma(
    const __nv_bfloat16* __restrict__ Qh_, const __nv_bfloat16* __restrict__ Ql_,
    const __nv_bfloat16* __restrict__ Kh_, const __nv_bfloat16* __restrict__ Kl_,
    const __nv_bfloat16* __restrict__ Vh_, const __nv_bfloat16* __restrict__ Vl_,
    __nv_bfloat16* __restrict__ Oh_, __nv_bfloat16* __restrict__ Ol_)
{
    extern __shared__ char sm[];
    const uint32_t sb = smem_u32(sm);

    const int qb = blockIdx.x, h = blockIdx.y, b = blockIdx.z;
    const int kvh = h >> 2;
    const int tid = threadIdx.x, lane = tid & 31, wid = tid >> 5;
    const int q0 = qb * 128;

    const size_t qg = ((size_t)(b * NH + h) * SEQ + q0) * HD;
    const size_t kg = (size_t)(b * NKV + kvh) * SEQ * HD;

    auto load_kv = [&](int jb, int buf) {
        const int k0 = jb * 64;
        const uint32_t base = sb + NKV0 + (uint32_t)buf * 4 * NKVT;
        for (int i = tid; i < 64 * 16; i += 256) {
            int r = i >> 4, cc = (i & 15) * 8;
            uint32_t so = (uint32_t)(r * ALDQ + cc) * 2;
            const size_t g = kg + (size_t)(k0 + r) * HD + cc;
            cp_async16(base + so,            Kh_ + g);
            cp_async16(base + NKVT + so,     Kl_ + g);
            cp_async16(base + 2 * NKVT + so, Vh_ + g);
            cp_async16(base + 3 * NKVT + so, Vl_ + g);
        }
        asm volatile("cp.async.commit_group;" ::: "memory");
    };

    for (int i = tid; i < 128 * 16; i += 256) {
        int r = i >> 4, cc = (i & 15) * 8;
        uint32_t so = (uint32_t)(r * ALDQ + cc) * 2;
        cp_async16(sb + NQH + so, Qh_ + qg + (size_t)r * HD + cc);
        cp_async16(sb + NQL + so, Ql_ + qg + (size_t)r * HD + cc);
    }
    load_kv(0, 0);

    const int a_row = ((lane >> 3) & 1) * 8 + (lane & 7);
    const int a_kh  = (lane >> 4) * 8;
    const int b_row = ((lane >> 4) & 1) * 8 + (lane & 7);
    const int b_kh  = ((lane >> 3) & 1) * 8;

    const int r0g = q0 + wid * 16 + (lane >> 2);
    const int cth = (lane & 3) * 2;

    float o[16][4];
#pragma unroll
    for (int i = 0; i < 16; i++)
#pragma unroll
        for (int q = 0; q < 4; q++) o[i][q] = 0.f;
    float m0 = -1e30f, m1 = -1e30f, l0 = 0.f, l1 = 0.f;

    const int ntiles = 2 * qb + 2;
    for (int jb = 0; jb < ntiles; jb++) {
        asm volatile("cp.async.wait_group 0;" ::: "memory");
        __syncthreads();
        if (jb + 1 < ntiles) load_kv(jb + 1, (jb + 1) & 1);

        const uint32_t kb = sb + NKV0 + (uint32_t)(jb & 1) * 4 * NKVT;
        const int k0 = jb * 64;

        float sa[8][4];
#pragma unroll
        for (int j = 0; j < 8; j++)
#pragma unroll
            for (int q = 0; q < 4; q++) sa[j][q] = 0.f;

#pragma unroll
        for (int ks = 0; ks < 8; ks++) {
            uint32_t qh[4], ql[4], bh[8][2], bl[8][2];
            const uint32_t qoff =
                (uint32_t)((wid * 16 + a_row) * ALDQ + ks * 16 + a_kh) * 2;
            ldsm_x4(qh[0], qh[1], qh[2], qh[3], sb + NQH + qoff);
            ldsm_x4(ql[0], ql[1], ql[2], ql[3], sb + NQL + qoff);
#pragma unroll
            for (int nb = 0; nb < 4; nb++) {
                const uint32_t koff =
                    (uint32_t)((nb * 16 + b_row) * ALDQ + ks * 16 + b_kh) * 2;
                ldsm_x4(bh[2 * nb][0], bh[2 * nb][1], bh[2 * nb + 1][0], bh[2 * nb + 1][1],
                        kb + koff);
                ldsm_x4(bl[2 * nb][0], bl[2 * nb][1], bl[2 * nb + 1][0], bl[2 * nb + 1][1],
                        kb + NKVT + koff);
            }
#pragma unroll
            for (int j = 0; j < 8; j++) {
                mma_bf16(sa[j], qh, bh[j]);
                mma_bf16(sa[j], qh, bl[j]);
                mma_bf16(sa[j], ql, bh[j]);
            }
        }

#pragma unroll
        for (int j = 0; j < 8; j++) {
            const int cb = k0 + j * 8 + cth;
            float s0 = sa[j][0] * SCL2E, s1 = sa[j][1] * SCL2E;
            float s2 = sa[j][2] * SCL2E, s3 = sa[j][3] * SCL2E;
            if (cb     > r0g)     s0 = -1e30f;
            if (cb + 1 > r0g)     s1 = -1e30f;
            if (cb     > r0g + 8) s2 = -1e30f;
            if (cb + 1 > r0g + 8) s3 = -1e30f;
            sa[j][0] = s0; sa[j][1] = s1; sa[j][2] = s2; sa[j][3] = s3;
        }

        float mx0 = -1e30f, mx1 = -1e30f;
#pragma unroll
        for (int j = 0; j < 8; j++) {
            mx0 = fmaxf(mx0, fmaxf(sa[j][0], sa[j][1]));
            mx1 = fmaxf(mx1, fmaxf(sa[j][2], sa[j][3]));
        }
        mx0 = fmaxf(mx0, __shfl_xor_sync(0xffffffff, mx0, 1));
        mx0 = fmaxf(mx0, __shfl_xor_sync(0xffffffff, mx0, 2));
        mx1 = fmaxf(mx1, __shfl_xor_sync(0xffffffff, mx1, 1));
        mx1 = fmaxf(mx1, __shfl_xor_sync(0xffffffff, mx1, 2));

        const float m0n = fmaxf(m0, mx0);
        const float m1n = fmaxf(m1, mx1);
        const float f0 = fexp2(m0 - m0n);
        const float f1 = fexp2(m1 - m1n);
        m0 = m0n; m1 = m1n;

        float sum0 = 0.f, sum1 = 0.f;
#pragma unroll
        for (int j = 0; j < 8; j++) {
            float p0 = fexp2(sa[j][0] - m0n);
            float p1 = fexp2(sa[j][1] - m0n);
            float p2 = fexp2(sa[j][2] - m1n);
            float p3 = fexp2(sa[j][3] - m1n);
            sum0 += p0 + p1; sum1 += p2 + p3;
            sa[j][0] = p0; sa[j][1] = p1; sa[j][2] = p2; sa[j][3] = p3;
        }
        sum0 += __shfl_xor_sync(0xffffffff, sum0, 1);
        sum0 += __shfl_xor_sync(0xffffffff, sum0, 2);
        sum1 += __shfl_xor_sync(0xffffffff, sum1, 1);
        sum1 += __shfl_xor_sync(0xffffffff, sum1, 2);
        l0 = l0 * f0 + sum0;
        l1 = l1 * f1 + sum1;

#pragma unroll
        for (int nt = 0; nt < 16; nt++) {
            o[nt][0] *= f0; o[nt][1] *= f0;
            o[nt][2] *= f1; o[nt][3] *= f1;
        }

        uint32_t ph[4][4], pl[4][4];
#pragma unroll
        for (int jk = 0; jk < 4; jk++) {
            const int j = 2 * jk, j2 = 2 * jk + 1;
            float v00 = sa[j][0],  v01 = sa[j][1],  v02 = sa[j][2],  v03 = sa[j][3];
            float v10 = sa[j2][0], v11 = sa[j2][1], v12 = sa[j2][2], v13 = sa[j2][3];
            ph[jk][0] = pack_bf16x2(v00, v01);
            ph[jk][1] = pack_bf16x2(v02, v03);
            ph[jk][2] = pack_bf16x2(v10, v11);
            ph[jk][3] = pack_bf16x2(v12, v13);
            pl[jk][0] = pack_bf16x2(v00 - __bfloat162float(__float2bfloat16(v00)),
                                    v01 - __bfloat162float(__float2bfloat16(v01)));
            pl[jk][1] = pack_bf16x2(v02 - __bfloat162float(__float2bfloat16(v02)),
                                    v03 - __bfloat162float(__float2bfloat16(v03)));
            pl[jk][2] = pack_bf16x2(v10 - __bfloat162float(__float2bfloat16(v10)),
                                    v11 - __bfloat162float(__float2bfloat16(v11)));
            pl[jk][3] = pack_bf16x2(v12 - __bfloat162float(__float2bfloat16(v12)),
                                    v13 - __bfloat162float(__float2bfloat16(v13)));
        }

        const uint32_t vbh = kb + 2 * NKVT;
        const uint32_t vbl = kb + 3 * NKVT;
#pragma unroll
        for (int kk = 0; kk < 4; kk++) {
#pragma unroll
            for (int half = 0; half < 2; half++) {
                uint32_t vh[8][2], vl[8][2];
#pragma unroll
                for (int nb = 0; nb < 4; nb++) {
                    const int vr = kk * 16 + ((lane >> 3) & 1) * 8 + (lane & 7);
                    const int vc = half * 64 + nb * 16 + ((lane >> 4) & 1) * 8;
                    const uint32_t off = (uint32_t)(vr * ALDQ + vc) * 2;
                    ldsm_x4_t(vh[2 * nb][0], vh[2 * nb][1],
                              vh[2 * nb + 1][0], vh[2 * nb + 1][1], vbh + off);
                    ldsm_x4_t(vl[2 * nb][0], vl[2 * nb][1],
                              vl[2 * nb + 1][0], vl[2 * nb + 1][1], vbl + off);
                }
#pragma unroll
                for (int nt = 0; nt < 8; nt++) {
                    const int ot = half * 8 + nt;
                    mma_bf16(o[ot], ph[kk], vh[nt]);
                    mma_bf16(o[ot], ph[kk], vl[nt]);
                    mma_bf16(o[ot], pl[kk], vh[nt]);
                }
            }
        }
    }

    const float i0 = 1.0f / l0;
    const float i1 = 1.0f / l1;
    const int row0 = q0 + wid * 16 + (lane >> 2);
    const size_t g0 = ((size_t)(b * SEQ + row0))     * (NH * HD) + h * HD;
    const size_t g1 = ((size_t)(b * SEQ + row0 + 8)) * (NH * HD) + h * HD;
#pragma unroll
    for (int nt = 0; nt < 16; nt++) {
        const int col = nt * 8 + cth;
        float v0 = o[nt][0] * i0, v1 = o[nt][1] * i0;
        float v2 = o[nt][2] * i1, v3 = o[nt][3] * i1;
        __nv_bfloat16 h0 = __float2bfloat16(v0), h1 = __float2bfloat16(v1);
        __nv_bfloat16 h2 = __float2bfloat16(v2), h3 = __float2bfloat16(v3);
        __nv_bfloat162 t;
        t.x = h0; t.y = h1; *(__nv_bfloat162*)(Oh_ + g0 + col) = t;
        t.x = __float2bfloat16(v0 - __bfloat162float(h0));
        t.y = __float2bfloat16(v1 - __bfloat162float(h1));
        *(__nv_bfloat162*)(Ol_ + g0 + col) = t;
        t.x = h2; t.y = h3; *(__nv_bfloat162*)(Oh_ + g1 + col) = t;
        t.x = __float2bfloat16(v2 - __bfloat162float(h2));
        t.y = __float2bfloat16(v3 - __bfloat162float(h3));
        *(__nv_bfloat162*)(Ol_ + g1 + col) = t;
    }
}

// ============================================================
// Launch
// ============================================================
extern "C" void kernel_launch(void* const* d_in, const int* in_sizes, int n_in,
                              void* d_out, int out_size)
{
    (void)in_sizes; (void)n_in; (void)out_size;
    const float* x  = (const float*)d_in[0];
    const float* Wq = (const float*)d_in[2];
    const float* Wk = (const float*)d_in[3];
    const float* Wv = (const float*)d_in[4];
    const float* Wo = (const float*)d_in[5];
    float* out = (float*)d_out;

    __nv_bfloat16 *xh, *xl, *wh, *wl, *woh, *wol;
    __nv_bfloat16 *qsh, *qsl, *ksh, *ksl, *vsh, *vsl, *oh, *ol;
    cudaGetSymbolAddress((void**)&xh, g_xh);   cudaGetSymbolAddress((void**)&xl, g_xl);
    cudaGetSymbolAddress((void**)&wh, g_wh);   cudaGetSymbolAddress((void**)&wl, g_wl);
    cudaGetSymbolAddress((void**)&woh, g_woh); cudaGetSymbolAddress((void**)&wol, g_wol);
    cudaGetSymbolAddress((void**)&qsh, g_qsh); cudaGetSymbolAddress((void**)&qsl, g_qsl);
    cudaGetSymbolAddress((void**)&ksh, g_ksh); cudaGetSymbolAddress((void**)&ksl, g_ksl);
    cudaGetSymbolAddress((void**)&vsh, g_vsh); cudaGetSymbolAddress((void**)&vsl, g_vsl);
    cudaGetSymbolAddress((void**)&oh, g_oh);   cudaGetSymbolAddress((void**)&ol, g_ol);

    const int M = BB * SEQ;
    const int NX = M * HIDN;

    cudaFuncSetAttribute(gemm3, cudaFuncAttributeMaxDynamicSharedMemorySize, G3_SMEM);
    cudaFuncSetAttribute(attn_hmma, cudaFuncAttributeMaxDynamicSharedMemorySize, NATTN_SMEM);

    // #1..#4: prep (ALL weight transposes before the fused GEMM)
    split_fp32<<<NX / 256, 256>>>(x, xh, xl, NX);
    transpose_split<<<dim3((NH * HD) / 32, HIDN / 32), dim3(32, 8)>>>(
        Wq, wh, wl, HIDN, NH * HD);
    transpose_split<<<dim3((NKV * HD) / 32, HIDN / 32), dim3(32, 8)>>>(
        Wk, wh + (size_t)2048 * HIDN, wl + (size_t)2048 * HIDN, HIDN, NKV * HD);
    transpose_split<<<dim3((NKV * HD) / 32, HIDN / 32), dim3(32, 8)>>>(
        Wv, wh + (size_t)2560 * HIDN, wl + (size_t)2560 * HIDN, HIDN, NKV * HD);
    // #5: fused QKV projection
    gemm3<<<dim3(NQKV / 128, M / 128), 128, G3_SMEM>>>(
        xh, xl, wh, wl, nullptr, qsh, qsl, ksh, ksl, vsh, vsl, NQKV, HIDN, 1);
    // #6: Wo transpose
    transpose_split<<<dim3(HIDN / 32, (NH * HD) / 32), dim3(32, 8)>>>(Wo, woh, wol, NH * HD, HIDN);
    // #7..#8: RoPE in-place
    rope_inplace<<<BB * NH * SEQ / 2,  128>>>(qsh, qsl);
    rope_inplace<<<BB * NKV * SEQ / 2, 128>>>(ksh, ksl);
    // #9: FA2 attention
    attn_hmma<<<dim3(SEQ / 128, NH, BB), 256, NATTN_SMEM>>>(qsh, qsl, ksh, ksl, vsh, vsl, oh, ol);
    // #10: output projection -> fp32 d_out
    gemm3<<<dim3(HIDN / 128, M / 128), 128, G3_SMEM>>>(
        oh, ol, woh, wol, out, nullptr, nullptr, nullptr, nullptr, nullptr, nullptr,
        HIDN, NH * HD, 0);
}

// round 16
// speedup vs baseline: 1.0102x; 1.0102x over previous
#include <cuda_runtime.h>
#include <cuda_bf16.h>
#include <math.h>
#include <cstdint>

#define BB   2
#define SEQ  2048
#define HIDN 2048
#define NH   16
#define NKV  4
#define HD   128

// ============================================================
// helpers
// ============================================================
__device__ __forceinline__ uint32_t smem_u32(const void* p) {
    uint32_t a;
    asm("{ .reg .u64 t; cvta.to.shared.u64 t, %1; cvt.u32.u64 %0, t; }" : "=r"(a) : "l"(p));
    return a;
}
__device__ __forceinline__ void ldsm_x4(uint32_t& r0, uint32_t& r1, uint32_t& r2, uint32_t& r3,
                                        uint32_t addr) {
    asm volatile("ldmatrix.sync.aligned.m8n8.x4.shared.b16 {%0,%1,%2,%3}, [%4];"
                 : "=r"(r0), "=r"(r1), "=r"(r2), "=r"(r3) : "r"(addr));
}
__device__ __forceinline__ void ldsm_x4_t(uint32_t& r0, uint32_t& r1, uint32_t& r2, uint32_t& r3,
                                          uint32_t addr) {
    asm volatile("ldmatrix.sync.aligned.m8n8.x4.trans.shared.b16 {%0,%1,%2,%3}, [%4];"
                 : "=r"(r0), "=r"(r1), "=r"(r2), "=r"(r3) : "r"(addr));
}
__device__ __forceinline__ void mma_bf16(float* c, const uint32_t* a, const uint32_t* b) {
    asm volatile("mma.sync.aligned.m16n8k16.row.col.f32.bf16.bf16.f32 "
                 "{%0,%1,%2,%3}, {%4,%5,%6,%7}, {%8,%9}, {%0,%1,%2,%3};"
                 : "+f"(c[0]), "+f"(c[1]), "+f"(c[2]), "+f"(c[3])
                 : "r"(a[0]), "r"(a[1]), "r"(a[2]), "r"(a[3]), "r"(b[0]), "r"(b[1]));
}
__device__ __forceinline__ void cp_async16(uint32_t saddr, const void* gptr) {
    asm volatile("cp.async.cg.shared.global [%0], [%1], 16;"
                 :: "r"(saddr), "l"(__cvta_generic_to_global(gptr)));
}
__device__ __forceinline__ float fexp2(float t) {
    t = fmaxf(t, -126.0f);
    float fi = floorf(t);
    float f = t - fi;
    float p =             1.5403530e-4f;
    p = fmaf(p, f, 1.3333558e-3f);
    p = fmaf(p, f, 9.6181291e-3f);
    p = fmaf(p, f, 5.5504109e-2f);
    p = fmaf(p, f, 2.4022651e-1f);
    p = fmaf(p, f, 6.9314718e-1f);
    p = fmaf(p, f, 1.0f);
    return p * __int_as_float(((int)fi + 127) << 23);
}
__device__ __forceinline__ uint32_t pack_bf16x2(float lo, float hi) {
    __nv_bfloat162 t;
    t.x = __float2bfloat16(lo);
    t.y = __float2bfloat16(hi);
    return *(uint32_t*)&t;
}

// -------- scratch (device globals) --------
__device__ __nv_bfloat16 g_xh[(size_t)BB * SEQ * HIDN], g_xl[(size_t)BB * SEQ * HIDN];
#define NQKV 3072
__device__ __nv_bfloat16 g_wh[(size_t)NQKV * HIDN], g_wl[(size_t)NQKV * HIDN];
__device__ __nv_bfloat16 g_woh[(size_t)NH * HD * HIDN], g_wol[(size_t)NH * HD * HIDN];

__device__ __nv_bfloat16 g_qsh[(size_t)BB * NH * SEQ * HD],  g_qsl[(size_t)BB * NH * SEQ * HD];
__device__ __nv_bfloat16 g_ksh[(size_t)BB * NKV * SEQ * HD], g_ksl[(size_t)BB * NKV * SEQ * HD];
__device__ __nv_bfloat16 g_vsh[(size_t)BB * NKV * SEQ * HD], g_vsl[(size_t)BB * NKV * SEQ * HD];
__device__ __nv_bfloat16 g_oh[(size_t)BB * SEQ * NH * HD],  g_ol[(size_t)BB * SEQ * NH * HD];

// ============================================================
// fp32 -> (hi, lo) bf16 split, vectorized x4
// ============================================================
__global__ void split_fp32(const float* __restrict__ x,
                           __nv_bfloat16* __restrict__ h, __nv_bfloat16* __restrict__ l, int n4)
{
    int i = blockIdx.x * blockDim.x + threadIdx.x;
    if (i < n4) {
        float4 v = ((const float4*)x)[i];
        __nv_bfloat16 h0 = __float2bfloat16(v.x), h1 = __float2bfloat16(v.y);
        __nv_bfloat16 h2 = __float2bfloat16(v.z), h3 = __float2bfloat16(v.w);
        __nv_bfloat162 a, b;
        a.x = h0; a.y = h1; b.x = h2; b.y = h3;
        ((__nv_bfloat162*)h)[2 * i]     = a;
        ((__nv_bfloat162*)h)[2 * i + 1] = b;
        a.x = __float2bfloat16(v.x - __bfloat162float(h0));
        a.y = __float2bfloat16(v.y - __bfloat162float(h1));
        b.x = __float2bfloat16(v.z - __bfloat162float(h2));
        b.y = __float2bfloat16(v.w - __bfloat162float(h3));
        ((__nv_bfloat162*)l)[2 * i]     = a;
        ((__nv_bfloat162*)l)[2 * i + 1] = b;
    }
}

// ============================================================
// W[K,N] fp32 -> Wt_hi/Wt_lo [N,K] bf16 (transpose + split)
// ============================================================
__global__ void transpose_split(const float* __restrict__ W,
                                __nv_bfloat16* __restrict__ Th, __nv_bfloat16* __restrict__ Tl,
                                int K, int N)
{
    __shared__ float t[32][33];
    const int n0 = blockIdx.x * 32, k0 = blockIdx.y * 32;
    const int tx = threadIdx.x, ty = threadIdx.y;
    for (int i = ty; i < 32; i += 8)
        t[i][tx] = W[(size_t)(k0 + i) * N + n0 + tx];
    __syncthreads();
    for (int i = ty; i < 32; i += 8) {
        float v = t[tx][i];
        __nv_bfloat16 hi = __float2bfloat16(v);
        float r = v - __bfloat162float(hi);
        Th[(size_t)(n0 + i) * K + k0 + tx] = hi;
        Tl[(size_t)(n0 + i) * K + k0 + tx] = __float2bfloat16(r);
    }
}

#define LDA 40

// ============================================================
// gemm3: 128x128 CTA tile, 4 warps (2x2) 64x64 warp tiles,
// BK=32, 2-stage cp.async, 2 CTAs/SM.
// TERM-OUTER MMA ordering: same-acc reuse distance = 8 MMAs.
// epi==0 -> fp32 row-major Cf; epi==1 -> fused QKV scatter.
// ============================================================
#define G3_TILE (128 * LDA * 2)
#define G3_STAGE (4 * G3_TILE)
#define G3_SMEM (2 * G3_STAGE)

__global__ void __launch_bounds__(128, 2) gemm3(
    const __nv_bfloat16* __restrict__ Ah_, const __nv_bfloat16* __restrict__ Al_,
    const __nv_bfloat16* __restrict__ Bh_, const __nv_bfloat16* __restrict__ Bl_,
    float* __restrict__ Cf,
    __nv_bfloat16* __restrict__ Qh, __nv_bfloat16* __restrict__ Ql,
    __nv_bfloat16* __restrict__ Kh, __nv_bfloat16* __restrict__ Kl,
    __nv_bfloat16* __restrict__ Vh, __nv_bfloat16* __restrict__ Vl,
    int Nd, int Kd, int epi)
{
    extern __shared__ char sm[];
    const uint32_t sb = smem_u32(sm);
    const int tid = threadIdx.x, lane = tid & 31, wid = tid >> 5;
    const int m0 = blockIdx.y * 128, n0 = blockIdx.x * 128;
    const int m_off = (wid >> 1) * 64;
    const int n_off = (wid & 1) * 64;

    const int r0 = tid >> 2;
    const int c8 = (tid & 3) * 8;

    const __nv_bfloat16* gp[4] = {
        Ah_ + (size_t)m0 * Kd, Al_ + (size_t)m0 * Kd,
        Bh_ + (size_t)n0 * Kd, Bl_ + (size_t)n0 * Kd };

    const int nchunk = Kd >> 5;

    auto load_chunk = [&](int c) {
        const int k0 = c << 5;
        const uint32_t stg = sb + (uint32_t)(c & 1) * G3_STAGE;
#pragma unroll
        for (int t = 0; t < 4; t++) {
#pragma unroll
            for (int p = 0; p < 4; p++) {
                const int r = r0 + p * 32;
                cp_async16(stg + (uint32_t)t * G3_TILE + (uint32_t)(r * LDA + c8) * 2,
                           gp[t] + (size_t)r * Kd + k0 + c8);
            }
        }
        asm volatile("cp.async.commit_group;" ::: "memory");
    };

    const int a_row = ((lane >> 3) & 1) * 8 + (lane & 7);
    const int a_kh  = (lane >> 4) * 8;
    const int b_row = ((lane >> 4) & 1) * 8 + (lane & 7);
    const int b_kh  = ((lane >> 3) & 1) * 8;

    float acc[4][8][4];
#pragma unroll
    for (int i = 0; i < 4; i++)
#pragma unroll
        for (int j = 0; j < 8; j++)
#pragma unroll
            for (int q = 0; q < 4; q++) acc[i][j][q] = 0.f;

    load_chunk(0);
    for (int c = 0; c < nchunk; c++) {
        if (c + 1 < nchunk) {
            load_chunk(c + 1);
            asm volatile("cp.async.wait_group 1;" ::: "memory");
        } else {
            asm volatile("cp.async.wait_group 0;" ::: "memory");
        }
        __syncthreads();

        const uint32_t stg = sb + (uint32_t)(c & 1) * G3_STAGE;
        const uint32_t sAh = stg;
        const uint32_t sAl = stg + G3_TILE;
        const uint32_t sBh = stg + 2 * G3_TILE;
        const uint32_t sBl = stg + 3 * G3_TILE;

#pragma unroll
        for (int ks = 0; ks < 2; ks++) {
            uint32_t ah[4][4], al[4][4];
#pragma unroll
            for (int mi = 0; mi < 4; mi++) {
                const uint32_t off =
                    (uint32_t)((m_off + mi * 16 + a_row) * LDA + ks * 16 + a_kh) * 2;
                ldsm_x4(ah[mi][0], ah[mi][1], ah[mi][2], ah[mi][3], sAh + off);
                ldsm_x4(al[mi][0], al[mi][1], al[mi][2], al[mi][3], sAl + off);
            }
#pragma unroll
            for (int nb = 0; nb < 4; nb++) {
                uint32_t bh[2][2], bl[2][2];
                const uint32_t off =
                    (uint32_t)((n_off + nb * 16 + b_row) * LDA + ks * 16 + b_kh) * 2;
                ldsm_x4(bh[0][0], bh[0][1], bh[1][0], bh[1][1], sBh + off);
                ldsm_x4(bl[0][0], bl[0][1], bl[1][0], bl[1][1], sBl + off);
                // term-outer: 8 independent accs per term; reuse distance = 8 MMAs
#pragma unroll
                for (int mi = 0; mi < 4; mi++) {
                    mma_bf16(acc[mi][2 * nb + 0], ah[mi], bh[0]);
                    mma_bf16(acc[mi][2 * nb + 1], ah[mi], bh[1]);
                }
#pragma unroll
                for (int mi = 0; mi < 4; mi++) {
                    mma_bf16(acc[mi][2 * nb + 0], ah[mi], bl[0]);
                    mma_bf16(acc[mi][2 * nb + 1], ah[mi], bl[1]);
                }
#pragma unroll
                for (int mi = 0; mi < 4; mi++) {
                    mma_bf16(acc[mi][2 * nb + 0], al[mi], bh[0]);
                    mma_bf16(acc[mi][2 * nb + 1], al[mi], bh[1]);
                }
            }
        }
        __syncthreads();
    }

    const int erow = lane >> 2, ecol = (lane & 3) * 2;
    if (epi == 0) {
#pragma unroll
        for (int mi = 0; mi < 4; mi++)
#pragma unroll
            for (int ni = 0; ni < 8; ni++) {
                const int row = m0 + m_off + mi * 16 + erow;
                const int col = n0 + n_off + ni * 8 + ecol;
                float2 v0 = make_float2(acc[mi][ni][0], acc[mi][ni][1]);
                float2 v1 = make_float2(acc[mi][ni][2], acc[mi][ni][3]);
                *(float2*)(Cf + (size_t)row * Nd + col)       = v0;
                *(float2*)(Cf + (size_t)(row + 8) * Nd + col) = v1;
            }
    } else {
        __nv_bfloat16 *Dh, *Dl;
        int hh, heads;
        {
            const int colbase = n0 + n_off;
            if (colbase < 2048)      { Dh = Qh; Dl = Ql; hh = colbase >> 7;          heads = NH; }
            else if (colbase < 2560) { Dh = Kh; Dl = Kl; hh = (colbase - 2048) >> 7; heads = NKV; }
            else                     { Dh = Vh; Dl = Vl; hh = (colbase - 2560) >> 7; heads = NKV; }
        }
#pragma unroll
        for (int mi = 0; mi < 4; mi++)
#pragma unroll
            for (int ni = 0; ni < 8; ni++) {
                const int d = ((n_off & 64) + ni * 8 + ecol) & 127;
#pragma unroll
                for (int rr = 0; rr < 2; rr++) {
                    const int row = m0 + m_off + mi * 16 + erow + rr * 8;
                    const int bb = row >> 11, s = row & (SEQ - 1);
                    const size_t g = ((size_t)(bb * heads + hh) * SEQ + s) * HD + d;
                    float v0 = acc[mi][ni][rr * 2 + 0];
                    float v1 = acc[mi][ni][rr * 2 + 1];
                    __nv_bfloat16 h0 = __float2bfloat16(v0);
                    __nv_bfloat16 h1 = __float2bfloat16(v1);
                    __nv_bfloat162 hp; hp.x = h0; hp.y = h1;
                    *(__nv_bfloat162*)(Dh + g) = hp;
                    __nv_bfloat162 lp;
                    lp.x = __float2bfloat16(v0 - __bfloat162float(h0));
                    lp.y = __float2bfloat16(v1 - __bfloat162float(h1));
                    *(__nv_bfloat162*)(Dl + g) = lp;
                }
            }
    }
}

// ============================================================
// RoPE in-place; 128 threads = 2 rows per block
// ============================================================
__global__ void rope_inplace(__nv_bfloat16* __restrict__ h, __nv_bfloat16* __restrict__ l)
{
    const int ty = threadIdx.x >> 6;
    const int idx = blockIdx.x * 2 + ty;
    const int s = idx & (SEQ - 1);
    const size_t base = (size_t)idx * HD;
    const int i = threadIdx.x & 63;

    float x0 = __bfloat162float(h[base + 2 * i])     + __bfloat162float(l[base + 2 * i]);
    float x1 = __bfloat162float(h[base + 2 * i + 1]) + __bfloat162float(l[base + 2 * i + 1]);
    float inv = exp2f(-(float)i * (13.287712379549449f / 64.f));
    float ang = (float)s * inv;
    float sn, cs;
    sincosf(ang, &sn, &cs);
    float o0 = x0 * cs - x1 * sn;
    float o1 = x0 * sn + x1 * cs;
    __syncthreads();
    __nv_bfloat16 h0 = __float2bfloat16(o0);
    __nv_bfloat16 h1 = __float2bfloat16(o1);
    h[base + i]      = h0;
    h[base + i + 64] = h1;
    l[base + i]      = __float2bfloat16(o0 - __bfloat162float(h0));
    l[base + i + 64] = __float2bfloat16(o1 - __bfloat162float(h1));
}

// ============================================================
// FA2-style HMMA flash attention (unchanged from R13)
// ============================================================
#define ALDQ 136
#define NQH 0
#define NQL (128 * ALDQ * 2)
#define NKV0 (2 * 128 * ALDQ * 2)
#define NKVT (64 * ALDQ * 2)
#define NATTN_SMEM (NKV0 + 8 * NKVT)

#define SCL2E 0.12751744f

__global__ void __launch_bounds__(256, 1) attn_hmma(
    const __nv_bfloat16* __restrict__ Qh_, const __nv_bfloat16* __restrict__ Ql_,
    const __nv_bfloat16* __restrict__ Kh_, const __nv_bfloat16* __restrict__ Kl_,
    const __nv_bfloat16* __restrict__ Vh_, const __nv_bfloat16* __restrict__ Vl_,
    __nv_bfloat16* __restrict__ Oh_, __nv_bfloat16* __restrict__ Ol_)
{
    extern __shared__ char sm[];
    const uint32_t sb = smem_u32(sm);

    const int qb = blockIdx.x, h = blockIdx.y, b = blockIdx.z;
    const int kvh = h >> 2;
    const int tid = threadIdx.x, lane = tid & 31, wid = tid >> 5;
    const int q0 = qb * 128;

    const size_t qg = ((size_t)(b * NH + h) * SEQ + q0) * HD;
    const size_t kg = (size_t)(b * NKV + kvh) * SEQ * HD;

    auto load_kv = [&](int jb, int buf) {
        const int k0 = jb * 64;
        const uint32_t base = sb + NKV0 + (uint32_t)buf * 4 * NKVT;
        for (int i = tid; i < 64 * 16; i += 256) {
            int r = i >> 4, cc = (i & 15) * 8;
            uint32_t so = (uint32_t)(r * ALDQ + cc) * 2;
            const size_t g = kg + (size_t)(k0 + r) * HD + cc;
            cp_async16(base + so,            Kh_ + g);
            cp_async16(base + NKVT + so,     Kl_ + g);
            cp_async16(base + 2 * NKVT + so, Vh_ + g);
            cp_async16(base + 3 * NKVT + so, Vl_ + g);
        }
        asm volatile("cp.async.commit_group;" ::: "memory");
    };

    for (int i = tid; i < 128 * 16; i += 256) {
        int r = i >> 4, cc = (i & 15) * 8;
        uint32_t so = (uint32_t)(r * ALDQ + cc) * 2;
        cp_async16(sb + NQH + so, Qh_ + qg + (size_t)r * HD + cc);
        cp_async16(sb + NQL + so, Ql_ + qg + (size_t)r * HD + cc);
    }
    load_kv(0, 0);

    const int a_row = ((lane >> 3) & 1) * 8 + (lane & 7);
    const int a_kh  = (lane >> 4) * 8;
    const int b_row = ((lane >> 4) & 1) * 8 + (lane & 7);
    const int b_kh  = ((lane >> 3) & 1) * 8;

    const int r0g = q0 + wid * 16 + (lane >> 2);
    const int cth = (lane & 3) * 2;

    float o[16][4];
#pragma unroll
    for (int i = 0; i < 16; i++)
#pragma unroll
        for (int q = 0; q < 4; q++) o[i][q] = 0.f;
    float m0 = -1e30f, m1 = -1e30f, l0 = 0.f, l1 = 0.f;

    const int ntiles = 2 * qb + 2;
    for (int jb = 0; jb < ntiles; jb++) {
        asm volatile("cp.async.wait_group 0;" ::: "memory");
        __syncthreads();
        if (jb + 1 < ntiles) load_kv(jb + 1, (jb + 1) & 1);

        const uint32_t kb = sb + NKV0 + (uint32_t)(jb & 1) * 4 * NKVT;
        const int k0 = jb * 64;

        float sa[8][4];
#pragma unroll
        for (int j = 0; j < 8; j++)
#pragma unroll
            for (int q = 0; q < 4; q++) sa[j][q] = 0.f;

#pragma unroll
        for (int ks = 0; ks < 8; ks++) {
            uint32_t qh[4], ql[4], bh[8][2], bl[8][2];
            const uint32_t qoff =
                (uint32_t)((wid * 16 + a_row) * ALDQ + ks * 16 + a_kh) * 2;
            ldsm_x4(qh[0], qh[1], qh[2], qh[3], sb + NQH + qoff);
            ldsm_x4(ql[0], ql[1], ql[2], ql[3], sb + NQL + qoff);
#pragma unroll
            for (int nb = 0; nb < 4; nb++) {
                const uint32_t koff =
                    (uint32_t)((nb * 16 + b_row) * ALDQ + ks * 16 + b_kh) * 2;
                ldsm_x4(bh[2 * nb][0], bh[2 * nb][1], bh[2 * nb + 1][0], bh[2 * nb + 1][1],
                        kb + koff);
                ldsm_x4(bl[2 * nb][0], bl[2 * nb][1], bl[2 * nb + 1][0], bl[2 * nb + 1][1],
                        kb + NKVT + koff);
            }
#pragma unroll
            for (int j = 0; j < 8; j++) {
                mma_bf16(sa[j], qh, bh[j]);
                mma_bf16(sa[j], qh, bl[j]);
                mma_bf16(sa[j], ql, bh[j]);
            }
        }

#pragma unroll
        for (int j = 0; j < 8; j++) {
            const int cb = k0 + j * 8 + cth;
            float s0 = sa[j][0] * SCL2E, s1 = sa[j][1] * SCL2E;
            float s2 = sa[j][2] * SCL2E, s3 = sa[j][3] * SCL2E;
            if (cb     > r0g)     s0 = -1e30f;
            if (cb + 1 > r0g)     s1 = -1e30f;
            if (cb     > r0g + 8) s2 = -1e30f;
            if (cb + 1 > r0g + 8) s3 = -1e30f;
            sa[j][0] = s0; sa[j][1] = s1; sa[j][2] = s2; sa[j][3] = s3;
        }

        float mx0 = -1e30f, mx1 = -1e30f;
#pragma unroll
        for (int j = 0; j < 8; j++) {
            mx0 = fmaxf(mx0, fmaxf(sa[j][0], sa[j][1]));
            mx1 = fmaxf(mx1, fmaxf(sa[j][2], sa[j][3]));
        }
        mx0 = fmaxf(mx0, __shfl_xor_sync(0xffffffff, mx0, 1));
        mx0 = fmaxf(mx0, __shfl_xor_sync(0xffffffff, mx0, 2));
        mx1 = fmaxf(mx1, __shfl_xor_sync(0xffffffff, mx1, 1));
        mx1 = fmaxf(mx1, __shfl_xor_sync(0xffffffff, mx1, 2));

        const float m0n = fmaxf(m0, mx0);
        const float m1n = fmaxf(m1, mx1);
        const float f0 = fexp2(m0 - m0n);
        const float f1 = fexp2(m1 - m1n);
        m0 = m0n; m1 = m1n;

        float sum0 = 0.f, sum1 = 0.f;
#pragma unroll
        for (int j = 0; j < 8; j++) {
            float p0 = fexp2(sa[j][0] - m0n);
            float p1 = fexp2(sa[j][1] - m0n);
            float p2 = fexp2(sa[j][2] - m1n);
            float p3 = fexp2(sa[j][3] - m1n);
            sum0 += p0 + p1; sum1 += p2 + p3;
            sa[j][0] = p0; sa[j][1] = p1; sa[j][2] = p2; sa[j][3] = p3;
        }
        sum0 += __shfl_xor_sync(0xffffffff, sum0, 1);
        sum0 += __shfl_xor_sync(0xffffffff, sum0, 2);
        sum1 += __shfl_xor_sync(0xffffffff, sum1, 1);
        sum1 += __shfl_xor_sync(0xffffffff, sum1, 2);
        l0 = l0 * f0 + sum0;
        l1 = l1 * f1 + sum1;

#pragma unroll
        for (int nt = 0; nt < 16; nt++) {
            o[nt][0] *= f0; o[nt][1] *= f0;
            o[nt][2] *= f1; o[nt][3] *= f1;
        }

        uint32_t ph[4][4], pl[4][4];
#pragma unroll
        for (int jk = 0; jk < 4; jk++) {
            const int j = 2 * jk, j2 = 2 * jk + 1;
            float v00 = sa[j][0],  v01 = sa[j][1],  v02 = sa[j][2],  v03 = sa[j][3];
            float v10 = sa[j2][0], v11 = sa[j2][1], v12 = sa[j2][2], v13 = sa[j2][3];
            ph[jk][0] = pack_bf16x2(v00, v01);
            ph[jk][1] = pack_bf16x2(v02, v03);
            ph[jk][2] = pack_bf16x2(v10, v11);
            ph[jk][3] = pack_bf16x2(v12, v13);
            pl[jk][0] = pack_bf16x2(v00 - __bfloat162float(__float2bfloat16(v00)),
                                    v01 - __bfloat162float(__float2bfloat16(v01)));
            pl[jk][1] = pack_bf16x2(v02 - __bfloat162float(__float2bfloat16(v02)),
                                    v03 - __bfloat162float(__float2bfloat16(v03)));
            pl[jk][2] = pack_bf16x2(v10 - __bfloat162float(__float2bfloat16(v10)),
                                    v11 - __bfloat162float(__float2bfloat16(v11)));
            pl[jk][3] = pack_bf16x2(v12 - __bfloat162float(__float2bfloat16(v12)),
                                    v13 - __bfloat162float(__float2bfloat16(v13)));
        }

        const uint32_t vbh = kb + 2 * NKVT;
        const uint32_t vbl = kb + 3 * NKVT;
#pragma unroll
        for (int kk = 0; kk < 4; kk++) {
#pragma unroll
            for (int half = 0; half < 2; half++) {
                uint32_t vh[8][2], vl[8][2];
#pragma unroll
                for (int nb = 0; nb < 4; nb++) {
                    const int vr = kk * 16 + ((lane >> 3) & 1) * 8 + (lane & 7);
                    const int vc = half * 64 + nb * 16 + ((lane >> 4) & 1) * 8;
                    const uint32_t off = (uint32_t)(vr * ALDQ + vc) * 2;
                    ldsm_x4_t(vh[2 * nb][0], vh[2 * nb][1],
                              vh[2 * nb + 1][0], vh[2 * nb + 1][1], vbh + off);
                    ldsm_x4_t(vl[2 * nb][0], vl[2 * nb][1],
                              vl[2 * nb + 1][0], vl[2 * nb + 1][1], vbl + off);
                }
#pragma unroll
                for (int nt = 0; nt < 8; nt++) {
                    const int ot = half * 8 + nt;
                    mma_bf16(o[ot], ph[kk], vh[nt]);
                    mma_bf16(o[ot], ph[kk], vl[nt]);
                    mma_bf16(o[ot], pl[kk], vh[nt]);
                }
            }
        }
    }

    const float i0 = 1.0f / l0;
    const float i1 = 1.0f / l1;
    const int row0 = q0 + wid * 16 + (lane >> 2);
    const size_t g0 = ((size_t)(b * SEQ + row0))     * (NH * HD) + h * HD;
    const size_t g1 = ((size_t)(b * SEQ + row0 + 8)) * (NH * HD) + h * HD;
#pragma unroll
    for (int nt = 0; nt < 16; nt++) {
        const int col = nt * 8 + cth;
        float v0 = o[nt][0] * i0, v1 = o[nt][1] * i0;
        float v2 = o[nt][2] * i1, v3 = o[nt][3] * i1;
        __nv_bfloat16 h0 = __float2bfloat16(v0), h1 = __float2bfloat16(v1);
        __nv_bfloat16 h2 = __float2bfloat16(v2), h3 = __float2bfloat16(v3);
        __nv_bfloat162 t;
        t.x = h0; t.y = h1; *(__nv_bfloat162*)(Oh_ + g0 + col) = t;
        t.x = __float2bfloat16(v0 - __bfloat162float(h0));
        t.y = __float2bfloat16(v1 - __bfloat162float(h1));
        *(__nv_bfloat162*)(Ol_ + g0 + col) = t;
        t.x = h2; t.y = h3; *(__nv_bfloat162*)(Oh_ + g1 + col) = t;
        t.x = __float2bfloat16(v2 - __bfloat162float(h2));
        t.y = __float2bfloat16(v3 - __bfloat162float(h3));
        *(__nv_bfloat162*)(Ol_ + g1 + col) = t;
    }
}

// ============================================================
// Launch
// ============================================================
extern "C" void kernel_launch(void* const* d_in, const int* in_sizes, int n_in,
                              void* d_out, int out_size)
{
    (void)in_sizes; (void)n_in; (void)out_size;
    const float* x  = (const float*)d_in[0];
    const float* Wq = (const float*)d_in[2];
    const float* Wk = (const float*)d_in[3];
    const float* Wv = (const float*)d_in[4];
    const float* Wo = (const float*)d_in[5];
    float* out = (float*)d_out;

    __nv_bfloat16 *xh, *xl, *wh, *wl, *woh, *wol;
    __nv_bfloat16 *qsh, *qsl, *ksh, *ksl, *vsh, *vsl, *oh, *ol;
    cudaGetSymbolAddress((void**)&xh, g_xh);   cudaGetSymbolAddress((void**)&xl, g_xl);
    cudaGetSymbolAddress((void**)&wh, g_wh);   cudaGetSymbolAddress((void**)&wl, g_wl);
    cudaGetSymbolAddress((void**)&woh, g_woh); cudaGetSymbolAddress((void**)&wol, g_wol);
    cudaGetSymbolAddress((void**)&qsh, g_qsh); cudaGetSymbolAddress((void**)&qsl, g_qsl);
    cudaGetSymbolAddress((void**)&ksh, g_ksh); cudaGetSymbolAddress((void**)&ksl, g_ksl);
    cudaGetSymbolAddress((void**)&vsh, g_vsh); cudaGetSymbolAddress((void**)&vsl, g_vsl);
    cudaGetSymbolAddress((void**)&oh, g_oh);   cudaGetSymbolAddress((void**)&ol, g_ol);

    const int M = BB * SEQ;
    const int NX = M * HIDN;

    cudaFuncSetAttribute(gemm3, cudaFuncAttributeMaxDynamicSharedMemorySize, G3_SMEM);
    cudaFuncSetAttribute(attn_hmma, cudaFuncAttributeMaxDynamicSharedMemorySize, NATTN_SMEM);

    // #1..#4: prep (ALL weight transposes before the fused GEMM)
    split_fp32<<<NX / 4 / 256, 256>>>(x, xh, xl, NX / 4);
    transpose_split<<<dim3((NH * HD) / 32, HIDN / 32), dim3(32, 8)>>>(
        Wq, wh, wl, HIDN, NH * HD);
    transpose_split<<<dim3((NKV * HD) / 32, HIDN / 32), dim3(32, 8)>>>(
        Wk, wh + (size_t)2048 * HIDN, wl + (size_t)2048 * HIDN, HIDN, NKV * HD);
    transpose_split<<<dim3((NKV * HD) / 32, HIDN / 32), dim3(32, 8)>>>(
        Wv, wh + (size_t)2560 * HIDN, wl + (size_t)2560 * HIDN, HIDN, NKV * HD);
    // #5: fused QKV projection
    gemm3<<<dim3(NQKV / 128, M / 128), 128, G3_SMEM>>>(
        xh, xl, wh, wl, nullptr, qsh, qsl, ksh, ksl, vsh, vsl, NQKV, HIDN, 1);
    // #6: Wo transpose
    transpose_split<<<dim3(HIDN / 32, (NH * HD) / 32), dim3(32, 8)>>>(Wo, woh, wol, NH * HD, HIDN);
    // #7..#8: RoPE in-place
    rope_inplace<<<BB * NH * SEQ / 2,  128>>>(qsh, qsl);
    rope_inplace<<<BB * NKV * SEQ / 2, 128>>>(ksh, ksl);
    // #9: FA2 attention
    attn_hmma<<<dim3(SEQ / 128, NH, BB), 256, NATTN_SMEM>>>(qsh, qsl, ksh, ksl, vsh, vsl, oh, ol);
    // #10: output projection -> fp32 d_out
    gemm3<<<dim3(HIDN / 128, M / 128), 128, G3_SMEM>>>(
        oh, ol, woh, wol, out, nullptr, nullptr, nullptr, nullptr, nullptr, nullptr,
        HIDN, NH * HD, 0);
}

// round 17
// speedup vs baseline: 1.2528x; 1.2401x over previous
#include <cuda_runtime.h>
#include <cuda_fp16.h>
#include <math.h>
#include <cstdint>

#define BB   2
#define SEQ  2048
#define HIDN 2048
#define NH   16
#define NKV  4
#define HD   128

// ============================================================
// helpers
// ============================================================
__device__ __forceinline__ uint32_t smem_u32(const void* p) {
    uint32_t a;
    asm("{ .reg .u64 t; cvta.to.shared.u64 t, %1; cvt.u32.u64 %0, t; }" : "=r"(a) : "l"(p));
    return a;
}
__device__ __forceinline__ void ldsm_x4(uint32_t& r0, uint32_t& r1, uint32_t& r2, uint32_t& r3,
                                        uint32_t addr) {
    asm volatile("ldmatrix.sync.aligned.m8n8.x4.shared.b16 {%0,%1,%2,%3}, [%4];"
                 : "=r"(r0), "=r"(r1), "=r"(r2), "=r"(r3) : "r"(addr));
}
__device__ __forceinline__ void ldsm_x4_t(uint32_t& r0, uint32_t& r1, uint32_t& r2, uint32_t& r3,
                                          uint32_t addr) {
    asm volatile("ldmatrix.sync.aligned.m8n8.x4.trans.shared.b16 {%0,%1,%2,%3}, [%4];"
                 : "=r"(r0), "=r"(r1), "=r"(r2), "=r"(r3) : "r"(addr));
}
__device__ __forceinline__ void mma_f16(float* c, const uint32_t* a, const uint32_t* b) {
    asm volatile("mma.sync.aligned.m16n8k16.row.col.f32.f16.f16.f32 "
                 "{%0,%1,%2,%3}, {%4,%5,%6,%7}, {%8,%9}, {%0,%1,%2,%3};"
                 : "+f"(c[0]), "+f"(c[1]), "+f"(c[2]), "+f"(c[3])
                 : "r"(a[0]), "r"(a[1]), "r"(a[2]), "r"(a[3]), "r"(b[0]), "r"(b[1]));
}
__device__ __forceinline__ void cp_async16(uint32_t saddr, const void* gptr) {
    asm volatile("cp.async.cg.shared.global [%0], [%1], 16;"
                 :: "r"(saddr), "l"(__cvta_generic_to_global(gptr)));
}
__device__ __forceinline__ float fexp2(float t) {
    t = fmaxf(t, -126.0f);
    float fi = floorf(t);
    float f = t - fi;
    float p =             1.5403530e-4f;
    p = fmaf(p, f, 1.3333558e-3f);
    p = fmaf(p, f, 9.6181291e-3f);
    p = fmaf(p, f, 5.5504109e-2f);
    p = fmaf(p, f, 2.4022651e-1f);
    p = fmaf(p, f, 6.9314718e-1f);
    p = fmaf(p, f, 1.0f);
    return p * __int_as_float(((int)fi + 127) << 23);
}
__device__ __forceinline__ uint32_t pack_h2(float lo, float hi) {
    __half2 t;
    t.x = __float2half_rn(lo);
    t.y = __float2half_rn(hi);
    return *(uint32_t*)&t;
}

// -------- scratch (device globals) --------
__device__ __half g_xh[(size_t)BB * SEQ * HIDN], g_xl[(size_t)BB * SEQ * HIDN];
#define NQKV 3072
__device__ __half g_wh[(size_t)NQKV * HIDN];                 // fused QKV weights, fp16 single
__device__ __half g_woh[(size_t)NH * HD * HIDN];             // Wo, fp16 single

__device__ __half g_qsh[(size_t)BB * NH * SEQ * HD],  g_qsl[(size_t)BB * NH * SEQ * HD];
__device__ __half g_ksh[(size_t)BB * NKV * SEQ * HD], g_ksl[(size_t)BB * NKV * SEQ * HD];
__device__ __half g_vsh[(size_t)BB * NKV * SEQ * HD], g_vsl[(size_t)BB * NKV * SEQ * HD];
__device__ __half g_oh[(size_t)BB * SEQ * NH * HD],  g_ol[(size_t)BB * SEQ * NH * HD];

// ============================================================
// fp32 -> (hi, lo) fp16 split, vectorized x4
// ============================================================
__global__ void split_fp32(const float* __restrict__ x,
                           __half* __restrict__ h, __half* __restrict__ l, int n4)
{
    int i = blockIdx.x * blockDim.x + threadIdx.x;
    if (i < n4) {
        float4 v = ((const float4*)x)[i];
        __half h0 = __float2half_rn(v.x), h1 = __float2half_rn(v.y);
        __half h2 = __float2half_rn(v.z), h3 = __float2half_rn(v.w);
        __half2 a, b;
        a.x = h0; a.y = h1; b.x = h2; b.y = h3;
        ((__half2*)h)[2 * i]     = a;
        ((__half2*)h)[2 * i + 1] = b;
        a.x = __float2half_rn(v.x - __half2float(h0));
        a.y = __float2half_rn(v.y - __half2float(h1));
        b.x = __float2half_rn(v.z - __half2float(h2));
        b.y = __float2half_rn(v.w - __half2float(h3));
        ((__half2*)l)[2 * i]     = a;
        ((__half2*)l)[2 * i + 1] = b;
    }
}

// ============================================================
// W[K,N] fp32 -> Wt [N,K] fp16 single-rounded (transpose)
// ============================================================
__global__ void transpose_half(const float* __restrict__ W,
                               __half* __restrict__ Th, int K, int N)
{
    __shared__ float t[32][33];
    const int n0 = blockIdx.x * 32, k0 = blockIdx.y * 32;
    const int tx = threadIdx.x, ty = threadIdx.y;
    for (int i = ty; i < 32; i += 8)
        t[i][tx] = W[(size_t)(k0 + i) * N + n0 + tx];
    __syncthreads();
    for (int i = ty; i < 32; i += 8)
        Th[(size_t)(n0 + i) * K + k0 + tx] = __float2half_rn(t[tx][i]);
}

#define LDA 40

// ============================================================
// gemm2: 128x128 CTA tile, 4 warps (2x2) 64x64 warp tiles,
// BK=32, 2-stage cp.async, 2 CTAs/SM.
// A 2-term fp16 (Ah, Al), B single fp16: C = Ah*Bh + Al*Bh.
// 3 smem tiles/stage. Term-outer MMA ordering.
// epi==0 -> fp32 row-major Cf; epi==1 -> fused QKV scatter (fp16 split).
// ============================================================
#define G2_TILE (128 * LDA * 2)       // 10240 B
#define G2_STAGE (3 * G2_TILE)        // 30720 B
#define G2_SMEM (2 * G2_STAGE)        // 61440 B (x2 CTAs = 120K/SM)

__global__ void __launch_bounds__(128, 2) gemm2(
    const __half* __restrict__ Ah_, const __half* __restrict__ Al_,
    const __half* __restrict__ Bh_,
    float* __restrict__ Cf,
    __half* __restrict__ Qh, __half* __restrict__ Ql,
    __half* __restrict__ Kh, __half* __restrict__ Kl,
    __half* __restrict__ Vh, __half* __restrict__ Vl,
    int Nd, int Kd, int epi)
{
    extern __shared__ char sm[];
    const uint32_t sb = smem_u32(sm);
    const int tid = threadIdx.x, lane = tid & 31, wid = tid >> 5;
    const int m0 = blockIdx.y * 128, n0 = blockIdx.x * 128;
    const int m_off = (wid >> 1) * 64;
    const int n_off = (wid & 1) * 64;

    const int r0 = tid >> 2;
    const int c8 = (tid & 3) * 8;

    const __half* gp[3] = {
        Ah_ + (size_t)m0 * Kd, Al_ + (size_t)m0 * Kd,
        Bh_ + (size_t)n0 * Kd };

    const int nchunk = Kd >> 5;

    auto load_chunk = [&](int c) {
        const int k0 = c << 5;
        const uint32_t stg = sb + (uint32_t)(c & 1) * G2_STAGE;
#pragma unroll
        for (int t = 0; t < 3; t++) {
#pragma unroll
            for (int p = 0; p < 4; p++) {
                const int r = r0 + p * 32;
                cp_async16(stg + (uint32_t)t * G2_TILE + (uint32_t)(r * LDA + c8) * 2,
                           gp[t] + (size_t)r * Kd + k0 + c8);
            }
        }
        asm volatile("cp.async.commit_group;" ::: "memory");
    };

    const int a_row = ((lane >> 3) & 1) * 8 + (lane & 7);
    const int a_kh  = (lane >> 4) * 8;
    const int b_row = ((lane >> 4) & 1) * 8 + (lane & 7);
    const int b_kh  = ((lane >> 3) & 1) * 8;

    float acc[4][8][4];
#pragma unroll
    for (int i = 0; i < 4; i++)
#pragma unroll
        for (int j = 0; j < 8; j++)
#pragma unroll
            for (int q = 0; q < 4; q++) acc[i][j][q] = 0.f;

    load_chunk(0);
    for (int c = 0; c < nchunk; c++) {
        if (c + 1 < nchunk) {
            load_chunk(c + 1);
            asm volatile("cp.async.wait_group 1;" ::: "memory");
        } else {
            asm volatile("cp.async.wait_group 0;" ::: "memory");
        }
        __syncthreads();

        const uint32_t stg = sb + (uint32_t)(c & 1) * G2_STAGE;
        const uint32_t sAh = stg;
        const uint32_t sAl = stg + G2_TILE;
        const uint32_t sBh = stg + 2 * G2_TILE;

#pragma unroll
        for (int ks = 0; ks < 2; ks++) {
            uint32_t ah[4][4], al[4][4];
#pragma unroll
            for (int mi = 0; mi < 4; mi++) {
                const uint32_t off =
                    (uint32_t)((m_off + mi * 16 + a_row) * LDA + ks * 16 + a_kh) * 2;
                ldsm_x4(ah[mi][0], ah[mi][1], ah[mi][2], ah[mi][3], sAh + off);
                ldsm_x4(al[mi][0], al[mi][1], al[mi][2], al[mi][3], sAl + off);
            }
#pragma unroll
            for (int nb = 0; nb < 4; nb++) {
                uint32_t bh[2][2];
                const uint32_t off =
                    (uint32_t)((n_off + nb * 16 + b_row) * LDA + ks * 16 + b_kh) * 2;
                ldsm_x4(bh[0][0], bh[0][1], bh[1][0], bh[1][1], sBh + off);
                // term-outer: 8 independent accs per term
#pragma unroll
                for (int mi = 0; mi < 4; mi++) {
                    mma_f16(acc[mi][2 * nb + 0], ah[mi], bh[0]);
                    mma_f16(acc[mi][2 * nb + 1], ah[mi], bh[1]);
                }
#pragma unroll
                for (int mi = 0; mi < 4; mi++) {
                    mma_f16(acc[mi][2 * nb + 0], al[mi], bh[0]);
                    mma_f16(acc[mi][2 * nb + 1], al[mi], bh[1]);
                }
            }
        }
        __syncthreads();
    }

    const int erow = lane >> 2, ecol = (lane & 3) * 2;
    if (epi == 0) {
#pragma unroll
        for (int mi = 0; mi < 4; mi++)
#pragma unroll
            for (int ni = 0; ni < 8; ni++) {
                const int row = m0 + m_off + mi * 16 + erow;
                const int col = n0 + n_off + ni * 8 + ecol;
                float2 v0 = make_float2(acc[mi][ni][0], acc[mi][ni][1]);
                float2 v1 = make_float2(acc[mi][ni][2], acc[mi][ni][3]);
                *(float2*)(Cf + (size_t)row * Nd + col)       = v0;
                *(float2*)(Cf + (size_t)(row + 8) * Nd + col) = v1;
            }
    } else {
        __half *Dh, *Dl;
        int hh, heads;
        {
            const int colbase = n0 + n_off;
            if (colbase < 2048)      { Dh = Qh; Dl = Ql; hh = colbase >> 7;          heads = NH; }
            else if (colbase < 2560) { Dh = Kh; Dl = Kl; hh = (colbase - 2048) >> 7; heads = NKV; }
            else                     { Dh = Vh; Dl = Vl; hh = (colbase - 2560) >> 7; heads = NKV; }
        }
#pragma unroll
        for (int mi = 0; mi < 4; mi++)
#pragma unroll
            for (int ni = 0; ni < 8; ni++) {
                const int d = ((n_off & 64) + ni * 8 + ecol) & 127;
#pragma unroll
                for (int rr = 0; rr < 2; rr++) {
                    const int row = m0 + m_off + mi * 16 + erow + rr * 8;
                    const int bb = row >> 11, s = row & (SEQ - 1);
                    const size_t g = ((size_t)(bb * heads + hh) * SEQ + s) * HD + d;
                    float v0 = acc[mi][ni][rr * 2 + 0];
                    float v1 = acc[mi][ni][rr * 2 + 1];
                    __half h0 = __float2half_rn(v0);
                    __half h1 = __float2half_rn(v1);
                    __half2 hp; hp.x = h0; hp.y = h1;
                    *(__half2*)(Dh + g) = hp;
                    __half2 lp;
                    lp.x = __float2half_rn(v0 - __half2float(h0));
                    lp.y = __float2half_rn(v1 - __half2float(h1));
                    *(__half2*)(Dl + g) = lp;
                }
            }
    }
}

// ============================================================
// RoPE in-place on split fp16 head-major rows; 2 rows/block
// ============================================================
__global__ void rope_inplace(__half* __restrict__ h, __half* __restrict__ l)
{
    const int ty = threadIdx.x >> 6;
    const int idx = blockIdx.x * 2 + ty;
    const int s = idx & (SEQ - 1);
    const size_t base = (size_t)idx * HD;
    const int i = threadIdx.x & 63;

    float x0 = __half2float(h[base + 2 * i])     + __half2float(l[base + 2 * i]);
    float x1 = __half2float(h[base + 2 * i + 1]) + __half2float(l[base + 2 * i + 1]);
    float inv = exp2f(-(float)i * (13.287712379549449f / 64.f));
    float ang = (float)s * inv;
    float sn, cs;
    sincosf(ang, &sn, &cs);
    float o0 = x0 * cs - x1 * sn;
    float o1 = x0 * sn + x1 * cs;
    __syncthreads();
    __half h0 = __float2half_rn(o0);
    __half h1 = __float2half_rn(o1);
    h[base + i]      = h0;
    h[base + i + 64] = h1;
    l[base + i]      = __float2half_rn(o0 - __half2float(h0));
    l[base + i + 64] = __float2half_rn(o1 - __half2float(h1));
}

// ============================================================
// FA2-style flash attention, fp16 3-term split (structure as R13)
// ============================================================
#define ALDQ 136
#define NQH 0
#define NQL (128 * ALDQ * 2)
#define NKV0 (2 * 128 * ALDQ * 2)
#define NKVT (64 * ALDQ * 2)
#define NATTN_SMEM (NKV0 + 8 * NKVT)

#define SCL2E 0.12751744f

__global__ void __launch_bounds__(256, 1) attn_hmma(
    const __half* __restrict__ Qh_, const __half* __restrict__ Ql_,
    const __half* __restrict__ Kh_, const __half* __restrict__ Kl_,
    const __half* __restrict__ Vh_, const __half* __restrict__ Vl_,
    __half* __restrict__ Oh_, __half* __restrict__ Ol_)
{
    extern __shared__ char sm[];
    const uint32_t sb = smem_u32(sm);

    const int qb = blockIdx.x, h = blockIdx.y, b = blockIdx.z;
    const int kvh = h >> 2;
    const int tid = threadIdx.x, lane = tid & 31, wid = tid >> 5;
    const int q0 = qb * 128;

    const size_t qg = ((size_t)(b * NH + h) * SEQ + q0) * HD;
    const size_t kg = (size_t)(b * NKV + kvh) * SEQ * HD;

    auto load_kv = [&](int jb, int buf) {
        const int k0 = jb * 64;
        const uint32_t base = sb + NKV0 + (uint32_t)buf * 4 * NKVT;
        for (int i = tid; i < 64 * 16; i += 256) {
            int r = i >> 4, cc = (i & 15) * 8;
            uint32_t so = (uint32_t)(r * ALDQ + cc) * 2;
            const size_t g = kg + (size_t)(k0 + r) * HD + cc;
            cp_async16(base + so,            Kh_ + g);
            cp_async16(base + NKVT + so,     Kl_ + g);
            cp_async16(base + 2 * NKVT + so, Vh_ + g);
            cp_async16(base + 3 * NKVT + so, Vl_ + g);
        }
        asm volatile("cp.async.commit_group;" ::: "memory");
    };

    for (int i = tid; i < 128 * 16; i += 256) {
        int r = i >> 4, cc = (i & 15) * 8;
        uint32_t so = (uint32_t)(r * ALDQ + cc) * 2;
        cp_async16(sb + NQH + so, Qh_ + qg + (size_t)r * HD + cc);
        cp_async16(sb + NQL + so, Ql_ + qg + (size_t)r * HD + cc);
    }
    load_kv(0, 0);

    const int a_row = ((lane >> 3) & 1) * 8 + (lane & 7);
    const int a_kh  = (lane >> 4) * 8;
    const int b_row = ((lane >> 4) & 1) * 8 + (lane & 7);
    const int b_kh  = ((lane >> 3) & 1) * 8;

    const int r0g = q0 + wid * 16 + (lane >> 2);
    const int cth = (lane & 3) * 2;

    float o[16][4];
#pragma unroll
    for (int i = 0; i < 16; i++)
#pragma unroll
        for (int q = 0; q < 4; q++) o[i][q] = 0.f;
    float m0 = -1e30f, m1 = -1e30f, l0 = 0.f, l1 = 0.f;

    const int ntiles = 2 * qb + 2;
    for (int jb = 0; jb < ntiles; jb++) {
        asm volatile("cp.async.wait_group 0;" ::: "memory");
        __syncthreads();
        if (jb + 1 < ntiles) load_kv(jb + 1, (jb + 1) & 1);

        const uint32_t kb = sb + NKV0 + (uint32_t)(jb & 1) * 4 * NKVT;
        const int k0 = jb * 64;

        float sa[8][4];
#pragma unroll
        for (int j = 0; j < 8; j++)
#pragma unroll
            for (int q = 0; q < 4; q++) sa[j][q] = 0.f;

#pragma unroll
        for (int ks = 0; ks < 8; ks++) {
            uint32_t qh[4], ql[4], bh[8][2], bl[8][2];
            const uint32_t qoff =
                (uint32_t)((wid * 16 + a_row) * ALDQ + ks * 16 + a_kh) * 2;
            ldsm_x4(qh[0], qh[1], qh[2], qh[3], sb + NQH + qoff);
            ldsm_x4(ql[0], ql[1], ql[2], ql[3], sb + NQL + qoff);
#pragma unroll
            for (int nb = 0; nb < 4; nb++) {
                const uint32_t koff =
                    (uint32_t)((nb * 16 + b_row) * ALDQ + ks * 16 + b_kh) * 2;
                ldsm_x4(bh[2 * nb][0], bh[2 * nb][1], bh[2 * nb + 1][0], bh[2 * nb + 1][1],
                        kb + koff);
                ldsm_x4(bl[2 * nb][0], bl[2 * nb][1], bl[2 * nb + 1][0], bl[2 * nb + 1][1],
                        kb + NKVT + koff);
            }
#pragma unroll
            for (int j = 0; j < 8; j++) {
                mma_f16(sa[j], qh, bh[j]);
                mma_f16(sa[j], qh, bl[j]);
                mma_f16(sa[j], ql, bh[j]);
            }
        }

#pragma unroll
        for (int j = 0; j < 8; j++) {
            const int cb = k0 + j * 8 + cth;
            float s0 = sa[j][0] * SCL2E, s1 = sa[j][1] * SCL2E;
            float s2 = sa[j][2] * SCL2E, s3 = sa[j][3] * SCL2E;
            if (cb     > r0g)     s0 = -1e30f;
            if (cb + 1 > r0g)     s1 = -1e30f;
            if (cb     > r0g + 8) s2 = -1e30f;
            if (cb + 1 > r0g + 8) s3 = -1e30f;
            sa[j][0] = s0; sa[j][1] = s1; sa[j][2] = s2; sa[j][3] = s3;
        }

        float mx0 = -1e30f, mx1 = -1e30f;
#pragma unroll
        for (int j = 0; j < 8; j++) {
            mx0 = fmaxf(mx0, fmaxf(sa[j][0], sa[j][1]));
            mx1 = fmaxf(mx1, fmaxf(sa[j][2], sa[j][3]));
        }
        mx0 = fmaxf(mx0, __shfl_xor_sync(0xffffffff, mx0, 1));
        mx0 = fmaxf(mx0, __shfl_xor_sync(0xffffffff, mx0, 2));
        mx1 = fmaxf(mx1, __shfl_xor_sync(0xffffffff, mx1, 1));
        mx1 = fmaxf(mx1, __shfl_xor_sync(0xffffffff, mx1, 2));

        const float m0n = fmaxf(m0, mx0);
        const float m1n = fmaxf(m1, mx1);
        const float f0 = fexp2(m0 - m0n);
        const float f1 = fexp2(m1 - m1n);
        m0 = m0n; m1 = m1n;

        float sum0 = 0.f, sum1 = 0.f;
#pragma unroll
        for (int j = 0; j < 8; j++) {
            float p0 = fexp2(sa[j][0] - m0n);
            float p1 = fexp2(sa[j][1] - m0n);
            float p2 = fexp2(sa[j][2] - m1n);
            float p3 = fexp2(sa[j][3] - m1n);
            sum0 += p0 + p1; sum1 += p2 + p3;
            sa[j][0] = p0; sa[j][1] = p1; sa[j][2] = p2; sa[j][3] = p3;
        }
        sum0 += __shfl_xor_sync(0xffffffff, sum0, 1);
        sum0 += __shfl_xor_sync(0xffffffff, sum0, 2);
        sum1 += __shfl_xor_sync(0xffffffff, sum1, 1);
        sum1 += __shfl_xor_sync(0xffffffff, sum1, 2);
        l0 = l0 * f0 + sum0;
        l1 = l1 * f1 + sum1;

#pragma unroll
        for (int nt = 0; nt < 16; nt++) {
            o[nt][0] *= f0; o[nt][1] *= f0;
            o[nt][2] *= f1; o[nt][3] *= f1;
        }

        uint32_t ph[4][4], pl[4][4];
#pragma unroll
        for (int jk = 0; jk < 4; jk++) {
            const int j = 2 * jk, j2 = 2 * jk + 1;
            float v00 = sa[j][0],  v01 = sa[j][1],  v02 = sa[j][2],  v03 = sa[j][3];
            float v10 = sa[j2][0], v11 = sa[j2][1], v12 = sa[j2][2], v13 = sa[j2][3];
            ph[jk][0] = pack_h2(v00, v01);
            ph[jk][1] = pack_h2(v02, v03);
            ph[jk][2] = pack_h2(v10, v11);
            ph[jk][3] = pack_h2(v12, v13);
            pl[jk][0] = pack_h2(v00 - __half2float(__float2half_rn(v00)),
                                v01 - __half2float(__float2half_rn(v01)));
            pl[jk][1] = pack_h2(v02 - __half2float(__float2half_rn(v02)),
                                v03 - __half2float(__float2half_rn(v03)));
            pl[jk][2] = pack_h2(v10 - __half2float(__float2half_rn(v10)),
                                v11 - __half2float(__float2half_rn(v11)));
            pl[jk][3] = pack_h2(v12 - __half2float(__float2half_rn(v12)),
                                v13 - __half2float(__float2half_rn(v13)));
        }

        const uint32_t vbh = kb + 2 * NKVT;
        const uint32_t vbl = kb + 3 * NKVT;
#pragma unroll
        for (int kk = 0; kk < 4; kk++) {
#pragma unroll
            for (int half = 0; half < 2; half++) {
                uint32_t vh[8][2], vl[8][2];
#pragma unroll
                for (int nb = 0; nb < 4; nb++) {
                    const int vr = kk * 16 + ((lane >> 3) & 1) * 8 + (lane & 7);
                    const int vc = half * 64 + nb * 16 + ((lane >> 4) & 1) * 8;
                    const uint32_t off = (uint32_t)(vr * ALDQ + vc) * 2;
                    ldsm_x4_t(vh[2 * nb][0], vh[2 * nb][1],
                              vh[2 * nb + 1][0], vh[2 * nb + 1][1], vbh + off);
                    ldsm_x4_t(vl[2 * nb][0], vl[2 * nb][1],
                              vl[2 * nb + 1][0], vl[2 * nb + 1][1], vbl + off);
                }
#pragma unroll
                for (int nt = 0; nt < 8; nt++) {
                    const int ot = half * 8 + nt;
                    mma_f16(o[ot], ph[kk], vh[nt]);
                    mma_f16(o[ot], ph[kk], vl[nt]);
                    mma_f16(o[ot], pl[kk], vh[nt]);
                }
            }
        }
    }

    const float i0 = 1.0f / l0;
    const float i1 = 1.0f / l1;
    const int row0 = q0 + wid * 16 + (lane >> 2);
    const size_t g0 = ((size_t)(b * SEQ + row0))     * (NH * HD) + h * HD;
    const size_t g1 = ((size_t)(b * SEQ + row0 + 8)) * (NH * HD) + h * HD;
#pragma unroll
    for (int nt = 0; nt < 16; nt++) {
        const int col = nt * 8 + cth;
        float v0 = o[nt][0] * i0, v1 = o[nt][1] * i0;
        float v2 = o[nt][2] * i1, v3 = o[nt][3] * i1;
        __half h0 = __float2half_rn(v0), h1 = __float2half_rn(v1);
        __half h2 = __float2half_rn(v2), h3 = __float2half_rn(v3);
        __half2 t;
        t.x = h0; t.y = h1; *(__half2*)(Oh_ + g0 + col) = t;
        t.x = __float2half_rn(v0 - __half2float(h0));
        t.y = __float2half_rn(v1 - __half2float(h1));
        *(__half2*)(Ol_ + g0 + col) = t;
        t.x = h2; t.y = h3; *(__half2*)(Oh_ + g1 + col) = t;
        t.x = __float2half_rn(v2 - __half2float(h2));
        t.y = __float2half_rn(v3 - __half2float(h3));
        *(__half2*)(Ol_ + g1 + col) = t;
    }
}

// ============================================================
// Launch
// ============================================================
extern "C" void kernel_launch(void* const* d_in, const int* in_sizes, int n_in,
                              void* d_out, int out_size)
{
    (void)in_sizes; (void)n_in; (void)out_size;
    const float* x  = (const float*)d_in[0];
    const float* Wq = (const float*)d_in[2];
    const float* Wk = (const float*)d_in[3];
    const float* Wv = (const float*)d_in[4];
    const float* Wo = (const float*)d_in[5];
    float* out = (float*)d_out;

    __half *xh, *xl, *wh, *woh;
    __half *qsh, *qsl, *ksh, *ksl, *vsh, *vsl, *oh, *ol;
    cudaGetSymbolAddress((void**)&xh, g_xh);   cudaGetSymbolAddress((void**)&xl, g_xl);
    cudaGetSymbolAddress((void**)&wh, g_wh);
    cudaGetSymbolAddress((void**)&woh, g_woh);
    cudaGetSymbolAddress((void**)&qsh, g_qsh); cudaGetSymbolAddress((void**)&qsl, g_qsl);
    cudaGetSymbolAddress((void**)&ksh, g_ksh); cudaGetSymbolAddress((void**)&ksl, g_ksl);
    cudaGetSymbolAddress((void**)&vsh, g_vsh); cudaGetSymbolAddress((void**)&vsl, g_vsl);
    cudaGetSymbolAddress((void**)&oh, g_oh);   cudaGetSymbolAddress((void**)&ol, g_ol);

    const int M = BB * SEQ;
    const int NX = M * HIDN;

    cudaFuncSetAttribute(gemm2, cudaFuncAttributeMaxDynamicSharedMemorySize, G2_SMEM);
    cudaFuncSetAttribute(attn_hmma, cudaFuncAttributeMaxDynamicSharedMemorySize, NATTN_SMEM);

    // prep: split x; transpose Wq/Wk/Wv into fused fp16 buffer (rows 0/2048/2560)
    split_fp32<<<NX / 4 / 256, 256>>>(x, xh, xl, NX / 4);
    transpose_half<<<dim3((NH * HD) / 32, HIDN / 32), dim3(32, 8)>>>(
        Wq, wh, HIDN, NH * HD);
    transpose_half<<<dim3((NKV * HD) / 32, HIDN / 32), dim3(32, 8)>>>(
        Wk, wh + (size_t)2048 * HIDN, HIDN, NKV * HD);
    transpose_half<<<dim3((NKV * HD) / 32, HIDN / 32), dim3(32, 8)>>>(
        Wv, wh + (size_t)2560 * HIDN, HIDN, NKV * HD);
    // fused QKV projection (2-term fp16)
    gemm2<<<dim3(NQKV / 128, M / 128), 128, G2_SMEM>>>(
        xh, xl, wh, nullptr, qsh, qsl, ksh, ksl, vsh, vsl, NQKV, HIDN, 1);
    // Wo transpose
    transpose_half<<<dim3(HIDN / 32, (NH * HD) / 32), dim3(32, 8)>>>(Wo, woh, NH * HD, HIDN);
    // RoPE in-place
    rope_inplace<<<BB * NH * SEQ / 2,  128>>>(qsh, qsl);
    rope_inplace<<<BB * NKV * SEQ / 2, 128>>>(ksh, ksl);
    // FA2 attention (3-term fp16)
    attn_hmma<<<dim3(SEQ / 128, NH, BB), 256, NATTN_SMEM>>>(qsh, qsl, ksh, ksl, vsh, vsl, oh, ol);
    // output projection (2-term fp16) -> fp32 d_out
    gemm2<<<dim3(HIDN / 128, M / 128), 128, G2_SMEM>>>(
        oh, ol, woh, out, nullptr, nullptr, nullptr, nullptr, nullptr, nullptr,
        HIDN, NH * HD, 0);
}